// round 1
// baseline (speedup 1.0000x reference)
#include <cuda_runtime.h>
#include <cuda_bf16.h>

#define BS   4
#define NH   8
#define SEQ  2048
#define DK   64
#define NP   129      // max_pos + 1
#define WSTR 66       // smem stride (floats) for w rows: even + conflict-free

// Scratch: q_dot_rpr table, layout [b][i][h][p]  (contiguous 1032 floats per (b,i))
__device__ float g_table[(size_t)BS * SEQ * NH * NP];

__device__ __forceinline__ unsigned long long fma2(unsigned long long a,
                                                   unsigned long long b,
                                                   unsigned long long c) {
    unsigned long long d;
    asm("fma.rn.f32x2 %0, %1, %2, %3;" : "=l"(d) : "l"(a), "l"(b), "l"(c));
    return d;
}

// ---------------------------------------------------------------------------
// Phase 1: table[b,i,h,p] = sum_k q[b,h,i,k] * w[p,k]
// grid = BS*NH*(SEQ/64) blocks, 256 threads.
// Each warp owns 8 i-rows; each lane owns p in {lane, lane+32, lane+64, lane+96};
// p=128 handled in a warp-reduce epilogue. Packed f32x2 FMAs over k.
// ---------------------------------------------------------------------------
__global__ void __launch_bounds__(256, 1)
proj_kernel(const float* __restrict__ q, const float* __restrict__ w) {
    extern __shared__ float sm[];
    float* sw = sm;                    // NP * WSTR floats
    float* sq = sm + NP * WSTR;        // 64 * DK floats (base is 8B aligned: NP*WSTR even)

    const int tid  = threadIdx.x;
    const int bh   = blockIdx.x >> 5;      // / 32 tiles
    const int tile = blockIdx.x & 31;
    const int b    = bh >> 3;
    const int h    = bh & 7;
    const int i0   = tile * 64;

    // load w [129][64] -> padded smem
    for (int idx = tid; idx < NP * DK; idx += 256) {
        int p = idx >> 6, k = idx & 63;
        sw[p * WSTR + k] = w[idx];
    }
    // load q tile [64][64]
    const float* qbase = q + ((size_t)(b * NH + h) * SEQ + i0) * DK;
    for (int idx = tid; idx < 64 * DK; idx += 256) {
        sq[idx] = qbase[idx];
    }
    __syncthreads();

    const int warp = tid >> 5, lane = tid & 31;
    const int ib = warp * 8;   // first local i-row of this warp

    unsigned long long acc[8][4];
#pragma unroll
    for (int ii = 0; ii < 8; ii++)
#pragma unroll
        for (int u = 0; u < 4; u++) acc[ii][u] = 0ULL;

#pragma unroll 2
    for (int k2 = 0; k2 < DK / 2; k2++) {
        unsigned long long wv[4];
#pragma unroll
        for (int u = 0; u < 4; u++)
            wv[u] = *reinterpret_cast<const unsigned long long*>(
                        &sw[(lane + 32 * u) * WSTR + 2 * k2]);
#pragma unroll
        for (int ii = 0; ii < 8; ii++) {
            unsigned long long qv = *reinterpret_cast<const unsigned long long*>(
                                        &sq[(ib + ii) * DK + 2 * k2]);
#pragma unroll
            for (int u = 0; u < 4; u++)
                acc[ii][u] = fma2(qv, wv[u], acc[ii][u]);
        }
    }

    // store p = 0..127
#pragma unroll
    for (int ii = 0; ii < 8; ii++) {
        const int i = i0 + ib + ii;
        float* trow = g_table + ((size_t)(b * SEQ + i) * NH + h) * NP;
#pragma unroll
        for (int u = 0; u < 4; u++) {
            float2 v = *reinterpret_cast<float2*>(&acc[ii][u]);
            trow[lane + 32 * u] = v.x + v.y;
        }
    }

    // epilogue: p = 128 via warp reduction
    const float* w128 = &sw[128 * WSTR];
#pragma unroll
    for (int ii = 0; ii < 8; ii++) {
        const int i = i0 + ib + ii;
        float v = sq[(ib + ii) * DK + lane]      * w128[lane] +
                  sq[(ib + ii) * DK + 32 + lane] * w128[32 + lane];
#pragma unroll
        for (int o = 16; o > 0; o >>= 1)
            v += __shfl_xor_sync(0xffffffffu, v, o);
        if (lane == 0)
            g_table[((size_t)(b * SEQ + i) * NH + h) * NP + 128] = v;
    }
}

// ---------------------------------------------------------------------------
// Phase 2: out[b,h,i,j] = table[b,i,h, min(dist[b,i,j],128)]
// grid = BS*SEQ blocks (one per (b,i)), 256 threads.
// 8 heads * 129 table entries cached in smem; dist read as int4; out written
// as float4. ~94% of pos values clip to 128 -> smem reads mostly broadcast.
// ---------------------------------------------------------------------------
__global__ void __launch_bounds__(256, 8)
gather_kernel(const int* __restrict__ dist, float* __restrict__ out) {
    __shared__ float t[NH * 132];

    const int blk = blockIdx.x;                 // b*SEQ + i
    const int tid = threadIdx.x;

    const float* trow = g_table + (size_t)blk * (NH * NP);
    for (int idx = tid; idx < NH * NP; idx += 256) {
        int h = idx / NP;
        int p = idx - h * NP;
        t[h * 132 + p] = trow[idx];
    }
    __syncthreads();

    const int b = blk >> 11;       // / SEQ
    const int i = blk & (SEQ - 1);

    const int4* drow = reinterpret_cast<const int4*>(dist + (size_t)blk * SEQ);

#pragma unroll
    for (int rep = 0; rep < 2; rep++) {
        const int jv = rep * 256 + tid;         // float4 / int4 index; j = 4*jv
        int4 d = drow[jv];
        const int p0 = min(d.x, 128);
        const int p1 = min(d.y, 128);
        const int p2 = min(d.z, 128);
        const int p3 = min(d.w, 128);
#pragma unroll
        for (int h = 0; h < NH; h++) {
            const float* th = t + h * 132;
            float4 v = make_float4(th[p0], th[p1], th[p2], th[p3]);
            float4* optr = reinterpret_cast<float4*>(
                out + ((size_t)(b * NH + h) * SEQ + i) * SEQ);
            optr[jv] = v;
        }
    }
}

extern "C" void kernel_launch(void* const* d_in, const int* in_sizes, int n_in,
                              void* d_out, int out_size) {
    const float* q    = (const float*)d_in[0];
    const int*   dist = (const int*)  d_in[1];
    const float* w    = (const float*)d_in[2];
    float*       out  = (float*)d_out;

    const int smem1 = (NP * WSTR + 64 * DK) * sizeof(float);  // ~50.4 KB
    cudaFuncSetAttribute(proj_kernel,
                         cudaFuncAttributeMaxDynamicSharedMemorySize, smem1);

    proj_kernel<<<BS * NH * (SEQ / 64), 256, smem1>>>(q, w);
    gather_kernel<<<BS * SEQ, 256>>>(dist, out);
}

// round 2
// speedup vs baseline: 1.1544x; 1.1544x over previous
#include <cuda_runtime.h>
#include <cuda_bf16.h>

#define BS   4
#define NH   8
#define SEQ  2048
#define DK   64
#define NP   129
#define TI   8          // i-rows per block
#define PSTR 132        // padded p stride in table / wT
#define NT   256        // threads per block

// smem layout (bytes):
//   swT : float2 [32][PSTR]   k-major transposed w   33792
//   sq  : float  [TI][NH][DK] q tile                 16384
//   t   : float  [TI][NH][PSTR] projection table     33792
#define SWT_F2   (32 * PSTR)                 // 4224 float2
#define SQ_F     (TI * NH * DK)              // 4096 floats
#define T_F      (TI * NH * PSTR)            // 8448 floats
#define SMEM_BYTES (SWT_F2 * 8 + SQ_F * 4 + T_F * 4)   // 83968

__device__ __forceinline__ unsigned long long fma2(unsigned long long a,
                                                   unsigned long long b,
                                                   unsigned long long c) {
    unsigned long long d;
    asm("fma.rn.f32x2 %0, %1, %2, %3;" : "=l"(d) : "l"(a), "l"(b), "l"(c));
    return d;
}

__global__ void __launch_bounds__(NT, 2)
fused_kernel(const float* __restrict__ q,
             const int*   __restrict__ dist,
             const float* __restrict__ w,
             float*       __restrict__ out) {
    extern __shared__ char smem_raw[];
    float2* swT = reinterpret_cast<float2*>(smem_raw);            // [32][PSTR]
    float*  sq  = reinterpret_cast<float*>(smem_raw + SWT_F2 * 8); // [TI][NH][DK]
    float*  tsm = sq + SQ_F;                                       // [TI][NH][PSTR]

    const int tid = threadIdx.x;
    const int bi  = blockIdx.x;           // 0..1023
    const int b   = bi >> 8;              // 256 blocks per batch
    const int i0  = (bi & 255) * TI;

    // ---- load w transposed: swT[k2][p] = (w[p][2k2], w[p][2k2+1]); pad p>=129 with 0
    {
        const float2* w2 = reinterpret_cast<const float2*>(w);
        for (int idx = tid; idx < 32 * PSTR; idx += NT) {
            const int k2 = idx / PSTR;
            const int p  = idx - k2 * PSTR;
            float2 v = make_float2(0.f, 0.f);
            if (p < NP) v = w2[p * 32 + k2];
            swT[idx] = v;
        }
    }
    // ---- load q tile: sq[r][h][k]
    {
        const float4* q4 = reinterpret_cast<const float4*>(q);
        float4* sq4 = reinterpret_cast<float4*>(sq);
        for (int idx = tid; idx < TI * NH * 16; idx += NT) {
            const int r  = idx >> 7;
            const int h  = (idx >> 4) & 7;
            const int kq = idx & 15;
            sq4[idx] = q4[(((size_t)(b * NH + h) * SEQ) + i0 + r) * 16 + kq];
        }
    }
    __syncthreads();

    // ---- projection: thread (r = tid>>5, p0 = tid&31) computes
    //      t[r][h][p0 + 32u] for h=0..7, u=0..3, plus p=128 (lane p0==0 stores)
    {
        const int r  = tid >> 5;
        const int p0 = tid & 31;
        const float2* sqf2 = reinterpret_cast<const float2*>(sq) + r * (NH * 32);

        unsigned long long acc[NH][5];
#pragma unroll
        for (int h = 0; h < NH; h++)
#pragma unroll
            for (int u = 0; u < 5; u++) acc[h][u] = 0ULL;

#pragma unroll 8
        for (int k2 = 0; k2 < 32; k2++) {
            const float2* wrow = swT + k2 * PSTR;
            unsigned long long wv[5];
#pragma unroll
            for (int u = 0; u < 4; u++)
                wv[u] = *reinterpret_cast<const unsigned long long*>(wrow + p0 + 32 * u);
            wv[4] = *reinterpret_cast<const unsigned long long*>(wrow + 128);
#pragma unroll
            for (int h = 0; h < NH; h++) {
                unsigned long long qv = *reinterpret_cast<const unsigned long long*>(
                                            sqf2 + h * 32 + k2);
#pragma unroll
                for (int u = 0; u < 5; u++)
                    acc[h][u] = fma2(qv, wv[u], acc[h][u]);
            }
        }

        float* trow = tsm + r * (NH * PSTR);
#pragma unroll
        for (int h = 0; h < NH; h++) {
#pragma unroll
            for (int u = 0; u < 4; u++) {
                float2 v = *reinterpret_cast<float2*>(&acc[h][u]);
                trow[h * PSTR + p0 + 32 * u] = v.x + v.y;
            }
            if (p0 == 0) {
                float2 v = *reinterpret_cast<float2*>(&acc[h][4]);
                trow[h * PSTR + 128] = v.x + v.y;
            }
        }
    }
    __syncthreads();

    // ---- gather: out[b,h,i,j] = t[i-i0][h][min(dist[b,i,j],128)]
#pragma unroll
    for (int il = 0; il < TI; il++) {
        const int4* drow = reinterpret_cast<const int4*>(
            dist + ((size_t)(b * SEQ + i0 + il)) * SEQ);
        const float* ti = tsm + il * (NH * PSTR);

#pragma unroll
        for (int rep = 0; rep < 2; rep++) {
            const int jv = rep * NT + tid;
            int4 d = __ldcs(&drow[jv]);
            const int pa = min(d.x, 128);
            const int pb = min(d.y, 128);
            const int pc = min(d.z, 128);
            const int pd = min(d.w, 128);
#pragma unroll
            for (int h = 0; h < NH; h++) {
                const float* th = ti + h * PSTR;
                float4 v = make_float4(th[pa], th[pb], th[pc], th[pd]);
                float4* op = reinterpret_cast<float4*>(
                    out + (((size_t)(b * NH + h) * SEQ) + i0 + il) * SEQ);
                __stcs(&op[jv], v);
            }
        }
    }
}

extern "C" void kernel_launch(void* const* d_in, const int* in_sizes, int n_in,
                              void* d_out, int out_size) {
    const float* q    = (const float*)d_in[0];
    const int*   dist = (const int*)  d_in[1];
    const float* w    = (const float*)d_in[2];
    float*       out  = (float*)d_out;

    cudaFuncSetAttribute(fused_kernel,
                         cudaFuncAttributeMaxDynamicSharedMemorySize, SMEM_BYTES);

    fused_kernel<<<BS * (SEQ / TI), NT, SMEM_BYTES>>>(q, dist, w, out);
}

// round 4
// speedup vs baseline: 1.2814x; 1.1100x over previous
#include <cuda_runtime.h>
#include <cuda_bf16.h>

#define BS    4
#define NH    8
#define SEQ   2048
#define DK    64
#define NP    129
#define TI    4          // i-rows per block
#define PSTR2 130        // float2 stride for swT rows
#define TSTR  130        // float stride for t rows
#define NT    256

// smem layout:
//   swT : float2 [32][PSTR2]     33280 B   (w transposed, k-major)
//   sq  : float  [TI][NH][DK]     8192 B
//   t   : float  [TI][NH][TSTR]  16640 B
#define SWT_BYTES (32 * PSTR2 * 8)
#define SQ_BYTES  (TI * NH * DK * 4)
#define T_BYTES   (TI * NH * TSTR * 4)
#define SMEM_BYTES (SWT_BYTES + SQ_BYTES + T_BYTES)   // 58112

__device__ __forceinline__ unsigned long long fma2(unsigned long long a,
                                                   unsigned long long b,
                                                   unsigned long long c) {
    unsigned long long d;
    asm("fma.rn.f32x2 %0, %1, %2, %3;" : "=l"(d) : "l"(a), "l"(b), "l"(c));
    return d;
}

__global__ void __launch_bounds__(NT, 3)
fused_kernel(const float* __restrict__ q,
             const int*   __restrict__ dist,
             const float* __restrict__ w,
             float*       __restrict__ out) {
    extern __shared__ char smem_raw[];
    float2* swT = reinterpret_cast<float2*>(smem_raw);                    // [32][PSTR2]
    float*  sq  = reinterpret_cast<float*>(smem_raw + SWT_BYTES);         // [TI][NH][DK]
    float*  tsm = reinterpret_cast<float*>(smem_raw + SWT_BYTES + SQ_BYTES); // [TI][NH][TSTR]

    const int tid = threadIdx.x;
    const int bi  = blockIdx.x;              // 0..2047
    const int b   = bi >> 9;                 // 512 blocks per batch
    const int i0  = (bi & 511) * TI;

    // ---- load w transposed: swT[k2][p] = (w[p][2k2], w[p][2k2+1]); pad with 0
    {
        const float2* w2 = reinterpret_cast<const float2*>(w);
        for (int idx = tid; idx < 32 * PSTR2; idx += NT) {
            const int k2 = idx / PSTR2;
            const int p  = idx - k2 * PSTR2;
            float2 v = make_float2(0.f, 0.f);
            if (p < NP) v = w2[p * 32 + k2];
            swT[idx] = v;
        }
    }
    // ---- load q tile: sq[r][h][k]
    {
        const float4* q4 = reinterpret_cast<const float4*>(q);
        float4* sq4 = reinterpret_cast<float4*>(sq);
        for (int idx = tid; idx < TI * NH * 16; idx += NT) {
            const int r  = idx >> 7;             // /128
            const int h  = (idx >> 4) & 7;
            const int kq = idx & 15;
            sq4[idx] = q4[(((size_t)(b * NH + h) * SEQ) + i0 + r) * 16 + kq];
        }
    }
    __syncthreads();

    // ---- projection: warp-pair per i-row, 4 heads per warp.
    //      thread = (r = warp>>1, hh = (warp&1)*4, p0 = lane);
    //      covers h in [hh,hh+4), p in {p0, p0+32, p0+64, p0+96, 128}
    {
        const int warp = tid >> 5, lane = tid & 31;
        const int r  = warp >> 1;
        const int hh = (warp & 1) * 4;
        const float2* sqf2 = reinterpret_cast<const float2*>(sq) + (r * NH + hh) * 32;

        unsigned long long acc[4][5];
#pragma unroll
        for (int hl = 0; hl < 4; hl++)
#pragma unroll
            for (int u = 0; u < 5; u++) acc[hl][u] = 0ULL;

#pragma unroll 8
        for (int k2 = 0; k2 < 32; k2++) {
            const float2* wrow = swT + k2 * PSTR2;
            unsigned long long wv[5];
#pragma unroll
            for (int u = 0; u < 4; u++)
                wv[u] = *reinterpret_cast<const unsigned long long*>(wrow + lane + 32 * u);
            wv[4] = *reinterpret_cast<const unsigned long long*>(wrow + 128);
#pragma unroll
            for (int hl = 0; hl < 4; hl++) {
                unsigned long long qv = *reinterpret_cast<const unsigned long long*>(
                                            sqf2 + hl * 32 + k2);
#pragma unroll
                for (int u = 0; u < 5; u++)
                    acc[hl][u] = fma2(qv, wv[u], acc[hl][u]);
            }
        }

#pragma unroll
        for (int hl = 0; hl < 4; hl++) {
            float* trow = tsm + (r * NH + hh + hl) * TSTR;
#pragma unroll
            for (int u = 0; u < 4; u++) {
                float2 v = *reinterpret_cast<float2*>(&acc[hl][u]);
                trow[lane + 32 * u] = v.x + v.y;
            }
            if (lane == 0) {
                float2 v = *reinterpret_cast<float2*>(&acc[hl][4]);
                trow[128] = v.x + v.y;
            }
        }
    }
    __syncthreads();

    // ---- gather: out[b,h,i,j] = t[i-i0][h][min(dist[b,i,j],128)]
    {
        // hoist all dist loads (MLP = 8)
        int4 dv[TI * 2];
#pragma unroll
        for (int il = 0; il < TI; il++) {
            const int4* drow = reinterpret_cast<const int4*>(
                dist + ((size_t)(b * SEQ + i0 + il)) * SEQ);
#pragma unroll
            for (int rep = 0; rep < 2; rep++)
                dv[il * 2 + rep] = __ldcs(&drow[rep * NT + tid]);
        }

#pragma unroll
        for (int il = 0; il < TI; il++) {
            const float* ti = tsm + il * (NH * TSTR);
#pragma unroll
            for (int rep = 0; rep < 2; rep++) {
                const int jv = rep * NT + tid;
                const int4 d = dv[il * 2 + rep];
                const int pa = min(d.x, 128);
                const int pb = min(d.y, 128);
                const int pc = min(d.z, 128);
                const int pd = min(d.w, 128);
#pragma unroll
                for (int h = 0; h < NH; h++) {
                    const float* th = ti + h * TSTR;
                    float4 v = make_float4(th[pa], th[pb], th[pc], th[pd]);
                    float4* op = reinterpret_cast<float4*>(
                        out + (((size_t)(b * NH + h) * SEQ) + i0 + il) * SEQ);
                    __stcs(&op[jv], v);
                }
            }
        }
    }
}

extern "C" void kernel_launch(void* const* d_in, const int* in_sizes, int n_in,
                              void* d_out, int out_size) {
    const float* q    = (const float*)d_in[0];
    const int*   dist = (const int*)  d_in[1];
    const float* w    = (const float*)d_in[2];
    float*       out  = (float*)d_out;

    cudaFuncSetAttribute(fused_kernel,
                         cudaFuncAttributeMaxDynamicSharedMemorySize, SMEM_BYTES);

    fused_kernel<<<BS * (SEQ / TI), NT, SMEM_BYTES>>>(q, dist, w, out);
}